// round 1
// baseline (speedup 1.0000x reference)
#include <cuda_runtime.h>
#include <cstdint>

// ---------------- scratch (device globals; no allocations allowed) ----------------
__device__ unsigned long long g_act1[1024 * 196];   // stage1 bits: [b][14x14], bit c = channel
__device__ unsigned long long g_act2[1024 * 49];    // stage2 bits: [b][7x7], bit c = channel
__device__ unsigned int       g_act3[1024 * 64];    // stage3 bits: [b][2048/32], bit = neuron%32
__device__ unsigned long long g_w2[64 * 9];         // conv2 weights: [o][tap], bit i = in-channel
__device__ unsigned long long g_fc1b[2048 * 49];    // fc1 weights: [o][p], bit c: feature c*49+p
__device__ unsigned int       g_fc2b[10 * 64];      // fc2 weights: [o][w], bit b: input w*32+b

// ---------------- weight packing ----------------
__global__ void k_packw2(const float* __restrict__ w) {
    int t = blockIdx.x * blockDim.x + threadIdx.x;
    if (t >= 576) return;
    int o = t / 9, tap = t % 9;
    unsigned long long word = 0ull;
    const float* base = w + o * 576 + tap;
    #pragma unroll 8
    for (int i = 0; i < 64; i++)
        if (base[i * 9] >= 0.f) word |= 1ull << i;
    g_w2[t] = word;
}

__global__ void k_packfc1(const float* __restrict__ w) {
    int t = blockIdx.x * blockDim.x + threadIdx.x;
    if (t >= 2048 * 49) return;
    int o = t / 49, p = t % 49;
    unsigned long long word = 0ull;
    const float* base = w + o * 3136 + p;
    #pragma unroll 8
    for (int c = 0; c < 64; c++)
        if (base[c * 49] >= 0.f) word |= 1ull << c;
    g_fc1b[t] = word;
}

__global__ void k_packfc2(const float* __restrict__ w) {
    int t = blockIdx.x * blockDim.x + threadIdx.x;
    if (t >= 640) return;
    int o = t / 64, wi = t % 64;
    unsigned word = 0u;
    const float* base = w + o * 2048 + wi * 32;
    #pragma unroll
    for (int b = 0; b < 32; b++)
        if (base[b] >= 0.f) word |= 1u << b;
    g_fc2b[t] = word;
}

// ---------------- stage 1: conv1(float x, +/-1 w) + bn1 + sign + maxpool2 ----------------
// grid = 1024 samples, block = 196 threads (one per pooled 14x14 pixel)
__global__ void k_conv1(const float* __restrict__ x, const float* __restrict__ w1,
                        const float* __restrict__ g1, const float* __restrict__ b1,
                        const float* __restrict__ m1, const float* __restrict__ v1) {
    __shared__ float ws[576];
    __shared__ float sm[64], ss[64], sb[64];
    int tid = threadIdx.x;
    for (int i = tid; i < 576; i += 196) {
        float w = w1[i];
        ws[i] = (w >= 0.f) ? 1.f : -1.f;
    }
    if (tid < 64) {
        sm[tid] = m1[tid];
        ss[tid] = g1[tid] * (1.0f / sqrtf(v1[tid] + 1e-5f));
        sb[tid] = b1[tid];
    }
    __syncthreads();

    int b = blockIdx.x;
    int py = tid / 14, px = tid % 14;
    const float* xb = x + b * 784;

    float patch[4][4];
    #pragma unroll
    for (int r = 0; r < 4; r++) {
        int yy = 2 * py - 1 + r; yy = yy < 0 ? 0 : (yy > 27 ? 27 : yy);
        #pragma unroll
        for (int c = 0; c < 4; c++) {
            int xx = 2 * px - 1 + c; xx = xx < 0 ? 0 : (xx > 27 ? 27 : xx);
            patch[r][c] = xb[yy * 28 + xx];
        }
    }

    unsigned long long word = 0ull;
    for (int ch = 0; ch < 64; ch++) {
        const float* wc = &ws[ch * 9];
        float m = sm[ch], s = ss[ch], bb = sb[ch];
        bool bit = false;
        #pragma unroll
        for (int r = 0; r < 2; r++) {
            #pragma unroll
            for (int c = 0; c < 2; c++) {
                float acc = 0.f;
                #pragma unroll
                for (int dy = 0; dy < 3; dy++)
                    #pragma unroll
                    for (int dx = 0; dx < 3; dx++)
                        acc += patch[r + dy][c + dx] * wc[dy * 3 + dx];
                bit |= (((acc - m) * s + bb) >= 0.f);
            }
        }
        if (bit) word |= 1ull << ch;
    }
    g_act1[b * 196 + py * 14 + px] = word;
}

// ---------------- stage 2: conv2 (xnor-popc) + bn2 + sign + maxpool2 ----------------
// grid = 256 blocks * 196 threads; each thread = (sample, pooled 7x7 pixel)
__global__ void k_conv2(const float* __restrict__ g2, const float* __restrict__ b2,
                        const float* __restrict__ m2, const float* __restrict__ v2) {
    __shared__ unsigned long long w2s[576];
    __shared__ float sm[64], ss[64], sb[64];
    int tid = threadIdx.x;
    for (int i = tid; i < 576; i += 196) w2s[i] = g_w2[i];
    if (tid < 64) {
        sm[tid] = m2[tid];
        ss[tid] = g2[tid] * (1.0f / sqrtf(v2[tid] + 1e-5f));
        sb[tid] = b2[tid];
    }
    __syncthreads();

    int b  = blockIdx.x * 4 + tid / 49;
    int pp = tid % 49;
    int py = pp / 7, px = pp % 7;
    const unsigned long long* ab = g_act1 + b * 196;

    unsigned long long patch[4][4];
    #pragma unroll
    for (int r = 0; r < 4; r++) {
        int yy = 2 * py - 1 + r; yy = yy < 0 ? 0 : (yy > 13 ? 13 : yy);
        #pragma unroll
        for (int c = 0; c < 4; c++) {
            int xx = 2 * px - 1 + c; xx = xx < 0 ? 0 : (xx > 13 ? 13 : xx);
            patch[r][c] = ab[yy * 14 + xx];
        }
    }

    unsigned long long word = 0ull;
    for (int o = 0; o < 64; o++) {
        const unsigned long long* wo = &w2s[o * 9];
        float m = sm[o], s = ss[o], bb = sb[o];
        bool bit = false;
        #pragma unroll
        for (int r = 0; r < 2; r++) {
            #pragma unroll
            for (int c = 0; c < 2; c++) {
                int d = 0;
                #pragma unroll
                for (int dy = 0; dy < 3; dy++)
                    #pragma unroll
                    for (int dx = 0; dx < 3; dx++)
                        d += __popcll(patch[r + dy][c + dx] ^ wo[dy * 3 + dx]);
                float sum = (float)(576 - 2 * d);
                bit |= (((sum - m) * s + bb) >= 0.f);
            }
        }
        if (bit) word |= 1ull << o;
    }
    g_act2[b * 49 + pp] = word;
}

// ---------------- stage 3: fc1 (xnor-popc GEMM) + bn3 + sign ----------------
// block = 256 threads computes 32 samples x 256 neurons
__global__ void k_fc1(const float* __restrict__ g3, const float* __restrict__ b3,
                      const float* __restrict__ m3, const float* __restrict__ v3) {
    __shared__ unsigned long long sAct[32 * 49];
    int tid = threadIdx.x;
    int sbase = blockIdx.y * 32;
    int jbase = blockIdx.x * 256;

    for (int i = tid; i < 32 * 49; i += 256) {
        int s = i / 49, k = i % 49;
        sAct[i] = g_act2[(sbase + s) * 49 + k];
    }
    __syncthreads();

    int j = jbase + tid;
    int acc[32];
    #pragma unroll
    for (int s = 0; s < 32; s++) acc[s] = 0;

    const unsigned long long* wrow = g_fc1b + j * 49;
    for (int k = 0; k < 49; k++) {
        unsigned long long w = wrow[k];
        #pragma unroll
        for (int s = 0; s < 32; s++)
            acc[s] += __popcll(w ^ sAct[s * 49 + k]);
    }

    float m  = m3[j];
    float sc = g3[j] * (1.0f / sqrtf(v3[j] + 1e-5f));
    float bb = b3[j];
    int wordIdx = j >> 5;   // same for all lanes in a warp

    #pragma unroll
    for (int s = 0; s < 32; s++) {
        float sum = (float)(3136 - 2 * acc[s]);
        bool bit = ((sum - m) * sc + bb) >= 0.f;
        unsigned mask = __ballot_sync(0xffffffffu, bit);
        if ((tid & 31) == 0) g_act3[(sbase + s) * 64 + wordIdx] = mask;
    }
}

// ---------------- stage 4: fc2 + scale ----------------
__global__ void k_fc2(const float* __restrict__ scale, float* __restrict__ out) {
    int idx = blockIdx.x * blockDim.x + threadIdx.x;
    if (idx >= 10240) return;
    int s = idx / 10, o = idx % 10;
    const unsigned* a = g_act3 + s * 64;
    const unsigned* w = g_fc2b + o * 64;
    int d = 0;
    #pragma unroll
    for (int k = 0; k < 64; k++) d += __popc(a[k] ^ w[k]);
    out[idx] = (float)(2048 - 2 * d) * scale[0];
}

// ---------------- launch ----------------
extern "C" void kernel_launch(void* const* d_in, const int* in_sizes, int n_in,
                              void* d_out, int out_size) {
    const float* x       = (const float*)d_in[0];
    const float* conv1_w = (const float*)d_in[1];
    const float* bn1_g   = (const float*)d_in[2];
    const float* bn1_b   = (const float*)d_in[3];
    const float* bn1_m   = (const float*)d_in[4];
    const float* bn1_v   = (const float*)d_in[5];
    const float* conv2_w = (const float*)d_in[6];
    const float* bn2_g   = (const float*)d_in[7];
    const float* bn2_b   = (const float*)d_in[8];
    const float* bn2_m   = (const float*)d_in[9];
    const float* bn2_v   = (const float*)d_in[10];
    const float* fc1_w   = (const float*)d_in[11];
    const float* bn3_g   = (const float*)d_in[12];
    const float* bn3_b   = (const float*)d_in[13];
    const float* bn3_m   = (const float*)d_in[14];
    const float* bn3_v   = (const float*)d_in[15];
    const float* fc2_w   = (const float*)d_in[16];
    const float* scale   = (const float*)d_in[17];
    float* out = (float*)d_out;

    // weight packing (independent of activations)
    k_packw2 <<<(576 + 255) / 256, 256>>>(conv2_w);
    k_packfc1<<<(2048 * 49 + 255) / 256, 256>>>(fc1_w);
    k_packfc2<<<(640 + 255) / 256, 256>>>(fc2_w);

    // stages (default stream serializes)
    k_conv1<<<1024, 196>>>(x, conv1_w, bn1_g, bn1_b, bn1_m, bn1_v);
    k_conv2<<<256, 196>>>(bn2_g, bn2_b, bn2_m, bn2_v);
    {
        dim3 grid(8, 32);   // 2048/256 neuron tiles, 1024/32 sample tiles
        k_fc1<<<grid, 256>>>(bn3_g, bn3_b, bn3_m, bn3_v);
    }
    k_fc2<<<(10240 + 255) / 256, 256>>>(scale, out);
}

// round 2
// speedup vs baseline: 1.0620x; 1.0620x over previous
#include <cuda_runtime.h>
#include <cstdint>

typedef unsigned long long u64;
typedef unsigned int u32;

// ---------------- scratch (device globals; no allocations allowed) ----------------
__device__ u64 g_act1[1024 * 196];    // stage1 bits: [b][14x14], bit c = channel
__device__ u64 g_act2T[49 * 1024];    // stage2 bits: [p][b], bit c = channel (k-major for fc1)
__device__ u32 g_act3[1024 * 64];     // stage3 bits: [b][2048/32]
__device__ u64 g_w2[64 * 9];          // conv2 weights: [o][tap], bit i = in-channel
__device__ u64 g_fc1bT[49 * 2048];    // fc1 weights: [p][o], bit c (feature c*49+p)
__device__ u32 g_fc2b[10 * 64];       // fc2 weights: [o][w], bit b: input w*32+b

// ---------------- f32x2 helpers ----------------
__device__ __forceinline__ u64 pk2(float lo, float hi) {
    u64 r; asm("mov.b64 %0, {%1,%2};" : "=l"(r) : "f"(lo), "f"(hi)); return r;
}
__device__ __forceinline__ void upk2(float& lo, float& hi, u64 v) {
    asm("mov.b64 {%0,%1}, %2;" : "=f"(lo), "=f"(hi) : "l"(v));
}
__device__ __forceinline__ u64 fma2(u64 a, u64 b, u64 c) {
    u64 d; asm("fma.rn.f32x2 %0, %1, %2, %3;" : "=l"(d) : "l"(a), "l"(b), "l"(c)); return d;
}

// ---------------- weight packing ----------------
__global__ void k_packw2(const float* __restrict__ w) {
    int t = blockIdx.x * blockDim.x + threadIdx.x;
    if (t >= 576) return;
    int o = t / 9, tap = t % 9;
    u64 word = 0ull;
    const float* base = w + o * 576 + tap;
    #pragma unroll 8
    for (int i = 0; i < 64; i++)
        if (base[i * 9] >= 0.f) word |= 1ull << i;
    g_w2[t] = word;
}

// one block per output neuron: coalesced row load -> smem -> pack (transposed store)
__global__ void k_packfc1(const float* __restrict__ w) {
    __shared__ float row[3136];
    int o = blockIdx.x;
    int tid = threadIdx.x;  // 128
    const float4* src = (const float4*)(w + o * 3136);
    for (int i = tid; i < 784; i += 128) ((float4*)row)[i] = src[i];
    __syncthreads();
    if (tid < 49) {
        u64 word = 0ull;
        #pragma unroll 8
        for (int c = 0; c < 64; c++)
            if (row[c * 49 + tid] >= 0.f) word |= 1ull << c;
        g_fc1bT[tid * 2048 + o] = word;
    }
}

__global__ void k_packfc2(const float* __restrict__ w) {
    int t = blockIdx.x * blockDim.x + threadIdx.x;
    if (t >= 640) return;
    int o = t / 64, wi = t % 64;
    u32 word = 0u;
    const float* base = w + o * 2048 + wi * 32;
    #pragma unroll
    for (int b = 0; b < 32; b++)
        if (base[b] >= 0.f) word |= 1u << b;
    g_fc2b[t] = word;
}

// ---------------- stage 1: conv1 + bn1 + sign + maxpool2 (f32x2 channel pairs) ----------------
// grid = 1024 samples, block = 196 threads (one per pooled 14x14 pixel)
__global__ void k_conv1(const float* __restrict__ x, const float* __restrict__ w1,
                        const float* __restrict__ g1, const float* __restrict__ b1,
                        const float* __restrict__ m1, const float* __restrict__ v1) {
    __shared__ float ws[9][64];           // [tap][ch] so channel pairs are contiguous
    __shared__ float sm[64], ss[64], sb[64];
    int tid = threadIdx.x;
    for (int i = tid; i < 576; i += 196) {
        int ch = i / 9, tap = i % 9;
        ws[tap][ch] = (w1[i] >= 0.f) ? 1.f : -1.f;
    }
    if (tid < 64) {
        sm[tid] = m1[tid];
        ss[tid] = g1[tid] * (1.0f / sqrtf(v1[tid] + 1e-5f));
        sb[tid] = b1[tid];
    }
    __syncthreads();

    int b = blockIdx.x;
    int py = tid / 14, px = tid % 14;
    const float* xb = x + b * 784;

    u64 p2[4][4];  // packed {x,x}
    #pragma unroll
    for (int r = 0; r < 4; r++) {
        int yy = 2 * py - 1 + r; yy = yy < 0 ? 0 : (yy > 27 ? 27 : yy);
        #pragma unroll
        for (int c = 0; c < 4; c++) {
            int xx = 2 * px - 1 + c; xx = xx < 0 ? 0 : (xx > 27 ? 27 : xx);
            float v = xb[yy * 28 + xx];
            p2[r][c] = pk2(v, v);
        }
    }

    const u64* wrow = (const u64*)&ws[0][0];   // [tap][32 pairs]
    u64 word = 0ull;
    #pragma unroll 4
    for (int cp = 0; cp < 32; cp++) {
        u64 wt[9];
        #pragma unroll
        for (int t = 0; t < 9; t++) wt[t] = wrow[t * 32 + cp];

        u64 a00 = 0, a01 = 0, a10 = 0, a11 = 0;
        #pragma unroll
        for (int dy = 0; dy < 3; dy++) {
            #pragma unroll
            for (int dx = 0; dx < 3; dx++) {
                int t = dy * 3 + dx;
                a00 = fma2(wt[t], p2[dy][dx],     a00);
                a01 = fma2(wt[t], p2[dy][dx + 1], a01);
                a10 = fma2(wt[t], p2[dy + 1][dx],     a10);
                a11 = fma2(wt[t], p2[dy + 1][dx + 1], a11);
            }
        }
        float f00l, f00h, f01l, f01h, f10l, f10h, f11l, f11h;
        upk2(f00l, f00h, a00); upk2(f01l, f01h, a01);
        upk2(f10l, f10h, a10); upk2(f11l, f11h, a11);

        int ch0 = 2 * cp, ch1 = 2 * cp + 1;
        // lane 0 (even channel)
        {
            float mx = fmaxf(fmaxf(f00l, f01l), fmaxf(f10l, f11l));
            float mn = fminf(fminf(f00l, f01l), fminf(f10l, f11l));
            float s = ss[ch0];
            float a = (s >= 0.f) ? mx : mn;
            if (((a - sm[ch0]) * s + sb[ch0]) >= 0.f) word |= (1ull << ch0);
        }
        // lane 1 (odd channel)
        {
            float mx = fmaxf(fmaxf(f00h, f01h), fmaxf(f10h, f11h));
            float mn = fminf(fminf(f00h, f01h), fminf(f10h, f11h));
            float s = ss[ch1];
            float a = (s >= 0.f) ? mx : mn;
            if (((a - sm[ch1]) * s + sb[ch1]) >= 0.f) word |= (1ull << ch1);
        }
    }
    g_act1[b * 196 + tid] = word;
}

// ---------------- stage 2: conv2 (xnor-popc) + bn2 + sign + maxpool2 ----------------
// grid = 256 blocks * 196 threads; thread = (sample, pooled 7x7 pixel)
__global__ void k_conv2(const float* __restrict__ g2, const float* __restrict__ b2,
                        const float* __restrict__ m2, const float* __restrict__ v2) {
    __shared__ u64 w2s[576];
    __shared__ float sm[64], ss[64], sb[64];
    int tid = threadIdx.x;
    for (int i = tid; i < 576; i += 196) w2s[i] = g_w2[i];
    if (tid < 64) {
        sm[tid] = m2[tid];
        ss[tid] = g2[tid] * (1.0f / sqrtf(v2[tid] + 1e-5f));
        sb[tid] = b2[tid];
    }
    __syncthreads();

    int b  = blockIdx.x * 4 + tid / 49;
    int pp = tid % 49;
    int py = pp / 7, px = pp % 7;
    const u64* ab = g_act1 + b * 196;

    u64 patch[4][4];
    #pragma unroll
    for (int r = 0; r < 4; r++) {
        int yy = 2 * py - 1 + r; yy = yy < 0 ? 0 : (yy > 13 ? 13 : yy);
        #pragma unroll
        for (int c = 0; c < 4; c++) {
            int xx = 2 * px - 1 + c; xx = xx < 0 ? 0 : (xx > 13 ? 13 : xx);
            patch[r][c] = ab[yy * 14 + xx];
        }
    }

    u64 word = 0ull;
    #pragma unroll 4
    for (int o = 0; o < 64; o++) {
        const u64* wo = &w2s[o * 9];
        int d[4];
        #pragma unroll
        for (int r = 0; r < 2; r++) {
            #pragma unroll
            for (int c = 0; c < 2; c++) {
                int dd = 0;
                #pragma unroll
                for (int dy = 0; dy < 3; dy++)
                    #pragma unroll
                    for (int dx = 0; dx < 3; dx++)
                        dd += __popcll(patch[r + dy][c + dx] ^ wo[dy * 3 + dx]);
                d[r * 2 + c] = dd;
            }
        }
        int dmn = min(min(d[0], d[1]), min(d[2], d[3]));
        int dmx = max(max(d[0], d[1]), max(d[2], d[3]));
        float s = ss[o];
        int dsel = (s >= 0.f) ? dmn : dmx;          // max conv-sum <=> min mismatches (s>=0)
        float sum = (float)(576 - 2 * dsel);
        if (((sum - sm[o]) * s + sb[o]) >= 0.f) word |= 1ull << o;
    }
    g_act2T[pp * 1024 + b] = word;   // k-major for fc1
}

// ---------------- stage 3: fc1 (xnor-popc GEMM, 64n x 128s tile, 4x8 reg tile) ----------------
extern __shared__ u64 smemf[];
__global__ void k_fc1(const float* __restrict__ g3, const float* __restrict__ b3,
                      const float* __restrict__ m3, const float* __restrict__ v3) {
    u64* sW = smemf;           // [49][64]
    u64* sA = smemf + 49 * 64; // [49][128]
    int tid = threadIdx.x;     // 256
    int jb = blockIdx.x * 64;
    int sbs = blockIdx.y * 128;

    // stage weights (coalesced rows of 64)
    {
        const ulonglong2* gw = (const ulonglong2*)g_fc1bT;
        ulonglong2* sw2 = (ulonglong2*)sW;
        for (int i = tid; i < 49 * 32; i += 256) {
            int k = i / 32, jj = i % 32;
            sw2[i] = gw[k * 1024 + (jb >> 1) + jj];
        }
    }
    // stage acts (coalesced rows of 128)
    {
        const ulonglong2* ga = (const ulonglong2*)g_act2T;
        ulonglong2* sa2 = (ulonglong2*)sA;
        for (int i = tid; i < 49 * 64; i += 256) {
            int k = i / 64, s2 = i % 64;
            sa2[i] = ga[k * 512 + (sbs >> 1) + s2];
        }
    }
    __syncthreads();

    int tj = tid & 15;         // 16 neuron groups (4 each)
    int ts = tid >> 4;         // 16 sample groups (8 each)

    int acc[4][8];
    #pragma unroll
    for (int i = 0; i < 4; i++)
        #pragma unroll
        for (int u = 0; u < 8; u++) acc[i][u] = 0;

    const ulonglong2* swv = (const ulonglong2*)sW;
    const ulonglong2* sav = (const ulonglong2*)sA;
    #pragma unroll 1
    for (int k = 0; k < 49; k++) {
        ulonglong2 w01 = swv[k * 32 + tj * 2];
        ulonglong2 w23 = swv[k * 32 + tj * 2 + 1];
        u64 wv[4] = {w01.x, w01.y, w23.x, w23.y};
        ulonglong2 a01 = sav[k * 64 + ts * 4];
        ulonglong2 a23 = sav[k * 64 + ts * 4 + 1];
        ulonglong2 a45 = sav[k * 64 + ts * 4 + 2];
        ulonglong2 a67 = sav[k * 64 + ts * 4 + 3];
        u64 av[8] = {a01.x, a01.y, a23.x, a23.y, a45.x, a45.y, a67.x, a67.y};
        #pragma unroll
        for (int i = 0; i < 4; i++)
            #pragma unroll
            for (int u = 0; u < 8; u++)
                acc[i][u] += __popcll(wv[i] ^ av[u]);
    }

    // BN + sign -> nibble per (thread, sample)
    float nm[4], nsc[4], nbb[4];
    #pragma unroll
    for (int i = 0; i < 4; i++) {
        int j = jb + tj * 4 + i;
        nm[i]  = m3[j];
        nsc[i] = g3[j] * (1.0f / sqrtf(v3[j] + 1e-5f));
        nbb[i] = b3[j];
    }
    u32 nib[8];
    #pragma unroll
    for (int u = 0; u < 8; u++) {
        u32 nv = 0;
        #pragma unroll
        for (int i = 0; i < 4; i++) {
            float sum = (float)(3136 - 2 * acc[i][u]);
            if (((sum - nm[i]) * nsc[i] + nbb[i]) >= 0.f) nv |= 1u << i;
        }
        nib[u] = nv;
    }
    __syncthreads();  // done with sA contents
    unsigned char* bb = (unsigned char*)sA;   // [128 samples][16 bytes]
    #pragma unroll
    for (int u = 0; u < 8; u++)
        bb[(ts * 8 + u) * 16 + tj] = (unsigned char)nib[u];
    __syncthreads();
    {
        int s = tid >> 1, w = tid & 1;
        u64 v = ((const u64*)bb)[s * 2 + w];
        u64 t = (v | (v >> 4)) & 0x00FF00FF00FF00FFull;
        t = (t | (t >> 8)) & 0x0000FFFF0000FFFFull;
        u32 out = (u32)(t | (t >> 16));
        g_act3[(sbs + s) * 64 + (jb >> 5) + w] = out;
    }
}

// ---------------- stage 4: fc2 + scale ----------------
__global__ void k_fc2(const float* __restrict__ scale, float* __restrict__ out) {
    int idx = blockIdx.x * blockDim.x + threadIdx.x;
    if (idx >= 10240) return;
    int s = idx / 10, o = idx % 10;
    const u32* a = g_act3 + s * 64;
    const u32* w = g_fc2b + o * 64;
    int d = 0;
    #pragma unroll
    for (int k = 0; k < 64; k++) d += __popc(a[k] ^ w[k]);
    out[idx] = (float)(2048 - 2 * d) * scale[0];
}

// ---------------- launch ----------------
extern "C" void kernel_launch(void* const* d_in, const int* in_sizes, int n_in,
                              void* d_out, int out_size) {
    const float* x       = (const float*)d_in[0];
    const float* conv1_w = (const float*)d_in[1];
    const float* bn1_g   = (const float*)d_in[2];
    const float* bn1_b   = (const float*)d_in[3];
    const float* bn1_m   = (const float*)d_in[4];
    const float* bn1_v   = (const float*)d_in[5];
    const float* conv2_w = (const float*)d_in[6];
    const float* bn2_g   = (const float*)d_in[7];
    const float* bn2_b   = (const float*)d_in[8];
    const float* bn2_m   = (const float*)d_in[9];
    const float* bn2_v   = (const float*)d_in[10];
    const float* fc1_w   = (const float*)d_in[11];
    const float* bn3_g   = (const float*)d_in[12];
    const float* bn3_b   = (const float*)d_in[13];
    const float* bn3_m   = (const float*)d_in[14];
    const float* bn3_v   = (const float*)d_in[15];
    const float* fc2_w   = (const float*)d_in[16];
    const float* scale   = (const float*)d_in[17];
    float* out = (float*)d_out;

    // weight packing (independent of activations)
    k_packw2 <<<3, 192>>>(conv2_w);
    k_packfc1<<<2048, 128>>>(fc1_w);
    k_packfc2<<<3, 256>>>(fc2_w);

    // stages (default stream serializes)
    k_conv1<<<1024, 196>>>(x, bn1_g ? conv1_w : conv1_w, bn1_g, bn1_b, bn1_m, bn1_v);
    k_conv2<<<256, 196>>>(bn2_g, bn2_b, bn2_m, bn2_v);

    cudaFuncSetAttribute(k_fc1, cudaFuncAttributeMaxDynamicSharedMemorySize, 76 * 1024);
    {
        dim3 grid(32, 8);   // 2048/64 neuron tiles, 1024/128 sample tiles
        k_fc1<<<grid, 256, 49 * 192 * 8>>>(bn3_g, bn3_b, bn3_m, bn3_v);
    }
    k_fc2<<<40, 256>>>(scale, out);
}

// round 3
// speedup vs baseline: 1.1188x; 1.0534x over previous
#include <cuda_runtime.h>
#include <cstdint>

typedef unsigned long long u64;
typedef unsigned int u32;

// ---------------- scratch ----------------
__device__ u64 g_act1[1024 * 196];    // [b][14x14], bit c = channel
__device__ u64 g_act2T[49 * 1024];    // [p][b], bit c = channel (k-major for fc1)
__device__ u32 g_act3[1024 * 64];     // [b][2048/32]
__device__ u64 g_w2[64 * 9];          // [o][tap], bit i = in-channel
__device__ u64 g_fc1bT[49 * 2048];    // [p][o], bit c (feature c*49+p)
__device__ u32 g_fc2b[10 * 64];       // [o][w], bit b

// ---------------- f32x2 helpers ----------------
__device__ __forceinline__ u64 pk2(float lo, float hi) {
    u64 r; asm("mov.b64 %0, {%1,%2};" : "=l"(r) : "f"(lo), "f"(hi)); return r;
}
__device__ __forceinline__ void upk2(float& lo, float& hi, u64 v) {
    asm("mov.b64 {%0,%1}, %2;" : "=f"(lo), "=f"(hi) : "l"(v));
}
__device__ __forceinline__ u64 fma2(u64 a, u64 b, u64 c) {
    u64 d; asm("fma.rn.f32x2 %0, %1, %2, %3;" : "=l"(d) : "l"(a), "l"(b), "l"(c)); return d;
}

// ---------------- weight packing ----------------
// merged small packs: conv2 (576 threads) + fc2 (640 threads)
__global__ void k_packsmall(const float* __restrict__ w2, const float* __restrict__ wf2) {
    int t = blockIdx.x * blockDim.x + threadIdx.x;
    if (t < 576) {
        int o = t / 9, tap = t % 9;
        u64 word = 0ull;
        const float* base = w2 + o * 576 + tap;
        #pragma unroll 8
        for (int i = 0; i < 64; i++)
            if (base[i * 9] >= 0.f) word |= 1ull << i;
        g_w2[t] = word;
    } else if (t < 576 + 640) {
        int tt = t - 576;
        int o = tt / 64, wi = tt % 64;
        u32 word = 0u;
        const float* base = wf2 + o * 2048 + wi * 32;
        #pragma unroll
        for (int b = 0; b < 32; b++)
            if (base[b] >= 0.f) word |= 1u << b;
        g_fc2b[tt] = word;
    }
}

// one block per output neuron: coalesced row load -> smem -> pack (transposed store)
__global__ void k_packfc1(const float* __restrict__ w) {
    __shared__ float row[3136];
    int o = blockIdx.x;
    int tid = threadIdx.x;  // 128
    const float4* src = (const float4*)(w + o * 3136);
    for (int i = tid; i < 784; i += 128) ((float4*)row)[i] = src[i];
    __syncthreads();
    if (tid < 49) {
        u64 word = 0ull;
        #pragma unroll 8
        for (int c = 0; c < 64; c++)
            if (row[c * 49 + tid] >= 0.f) word |= 1ull << c;
        g_fc1bT[tid * 2048 + o] = word;
    }
}

// ---------------- stage 1: conv1 + bn1 + sign + maxpool2 ----------------
// 2 threads per pooled pixel (h = pool row). block = 416 (392 active), grid = 1024
__global__ void __launch_bounds__(416, 3)
k_conv1(const float* __restrict__ x, const float* __restrict__ w1,
        const float* __restrict__ g1, const float* __restrict__ b1,
        const float* __restrict__ m1, const float* __restrict__ v1) {
    __shared__ float ws[9][64];           // [tap][ch]: channel pairs contiguous
    __shared__ float sm[64], ss[64], sb[64];
    __shared__ u64 smask;
    int tid = threadIdx.x;
    for (int i = tid; i < 576; i += 416) {
        int ch = i / 9, tap = i % 9;
        ws[tap][ch] = (w1[i] >= 0.f) ? 1.f : -1.f;
    }
    if (tid < 64) {
        sm[tid] = m1[tid];
        ss[tid] = g1[tid] * (1.0f / sqrtf(v1[tid] + 1e-5f));
        sb[tid] = b1[tid];
    }
    __syncthreads();
    if (tid == 0) {
        u64 mk = 0ull;
        for (int c = 0; c < 64; c++) if (ss[c] >= 0.f) mk |= 1ull << c;
        smask = mk;
    }
    __syncthreads();

    int b = blockIdx.x;
    int t = tid < 392 ? tid : 391;
    int p = t >> 1, h = t & 1;
    int py = p / 14, px = p % 14;
    const float* xb = x + b * 784;

    u64 P[3][4];   // packed {v,v}, rows r0..r0+2
    #pragma unroll
    for (int r = 0; r < 3; r++) {
        int yy = 2 * py - 1 + h + r; yy = yy < 0 ? 0 : (yy > 27 ? 27 : yy);
        #pragma unroll
        for (int c = 0; c < 4; c++) {
            int xx = 2 * px - 1 + c; xx = xx < 0 ? 0 : (xx > 27 ? 27 : xx);
            float v = xb[yy * 28 + xx];
            P[r][c] = pk2(v, v);
        }
    }

    const u64* wrow = (const u64*)&ws[0][0];   // [tap][32 pairs]
    u64 wloc = 0ull;
    #pragma unroll 2
    for (int cp = 0; cp < 32; cp++) {
        u64 wt[9];
        #pragma unroll
        for (int k = 0; k < 9; k++) wt[k] = wrow[k * 32 + cp];
        u64 a0 = 0, a1 = 0;
        #pragma unroll
        for (int dy = 0; dy < 3; dy++) {
            #pragma unroll
            for (int dx = 0; dx < 3; dx++) {
                int k = dy * 3 + dx;
                a0 = fma2(wt[k], P[dy][dx],     a0);
                a1 = fma2(wt[k], P[dy][dx + 1], a1);
            }
        }
        float f0l, f0h, f1l, f1h;
        upk2(f0l, f0h, a0); upk2(f1l, f1h, a1);
        int ch0 = 2 * cp, ch1 = ch0 + 1;
        {
            float mx = fmaxf(f0l, f1l), mn = fminf(f0l, f1l);
            float s = ss[ch0];
            float a = (s >= 0.f) ? mx : mn;
            if (((a - sm[ch0]) * s + sb[ch0]) >= 0.f) wloc |= 1ull << ch0;
        }
        {
            float mx = fmaxf(f0h, f1h), mn = fminf(f0h, f1h);
            float s = ss[ch1];
            float a = (s >= 0.f) ? mx : mn;
            if (((a - sm[ch1]) * s + sb[ch1]) >= 0.f) wloc |= 1ull << ch1;
        }
    }
    u64 other = __shfl_xor_sync(0xffffffffu, wloc, 1);
    u64 mk = smask;
    u64 wfin = ((wloc | other) & mk) | ((wloc & other) & ~mk);
    if (tid < 392 && h == 0) g_act1[b * 196 + p] = wfin;
}

// ---------------- stage 2: conv2 (xnor-popc) + bn2 + sign + maxpool2 ----------------
// 2 threads per pooled pixel, 4 samples/block. block = 416 (392 active), grid = 256
__global__ void __launch_bounds__(416, 3)
k_conv2(const float* __restrict__ g2, const float* __restrict__ b2,
        const float* __restrict__ m2, const float* __restrict__ v2) {
    __shared__ u64 w2s[576];
    __shared__ float sm[64], ss[64], sb[64];
    __shared__ u64 smask;
    int tid = threadIdx.x;
    for (int i = tid; i < 576; i += 416) w2s[i] = g_w2[i];
    if (tid < 64) {
        sm[tid] = m2[tid];
        ss[tid] = g2[tid] * (1.0f / sqrtf(v2[tid] + 1e-5f));
        sb[tid] = b2[tid];
    }
    __syncthreads();
    if (tid == 0) {
        u64 mk = 0ull;
        for (int c = 0; c < 64; c++) if (ss[c] >= 0.f) mk |= 1ull << c;
        smask = mk;
    }
    __syncthreads();

    int t = tid < 392 ? tid : 391;
    int ls = t / 98, rem = t % 98;
    int p = rem >> 1, h = rem & 1;
    int b = blockIdx.x * 4 + ls;
    int py = p / 7, px = p % 7;
    const u64* ab = g_act1 + b * 196;

    u64 P[3][4];
    #pragma unroll
    for (int r = 0; r < 3; r++) {
        int yy = 2 * py - 1 + h + r; yy = yy < 0 ? 0 : (yy > 13 ? 13 : yy);
        #pragma unroll
        for (int c = 0; c < 4; c++) {
            int xx = 2 * px - 1 + c; xx = xx < 0 ? 0 : (xx > 13 ? 13 : xx);
            P[r][c] = ab[yy * 14 + xx];
        }
    }

    u64 wloc = 0ull;
    #pragma unroll 2
    for (int o = 0; o < 64; o++) {
        const u64* wo = &w2s[o * 9];
        int d0 = 0, d1 = 0;
        #pragma unroll
        for (int dy = 0; dy < 3; dy++) {
            #pragma unroll
            for (int dx = 0; dx < 3; dx++) {
                u64 w = wo[dy * 3 + dx];
                d0 += __popcll(P[dy][dx]     ^ w);
                d1 += __popcll(P[dy][dx + 1] ^ w);
            }
        }
        int dmn = min(d0, d1), dmx = max(d0, d1);
        float s = ss[o];
        int dsel = (s >= 0.f) ? dmn : dmx;
        float sum = (float)(576 - 2 * dsel);
        if (((sum - sm[o]) * s + sb[o]) >= 0.f) wloc |= 1ull << o;
    }
    u64 other = __shfl_xor_sync(0xffffffffu, wloc, 1);
    u64 mk = smask;
    u64 wfin = ((wloc | other) & mk) | ((wloc & other) & ~mk);
    if (tid < 392 && h == 0) g_act2T[p * 1024 + b] = wfin;   // k-major for fc1
}

// ---------------- stage 3: fc1 (xnor-popc GEMM, 64n x 64s tile, 4x4 reg tile) ----------------
extern __shared__ u64 smemf[];
__global__ void k_fc1(const float* __restrict__ g3, const float* __restrict__ b3,
                      const float* __restrict__ m3, const float* __restrict__ v3) {
    u64* sW = smemf;           // [49][64]
    u64* sA = smemf + 49 * 64; // [49][64]
    int tid = threadIdx.x;     // 256
    int jb = blockIdx.x * 64;
    int sbs = blockIdx.y * 64;

    {
        const ulonglong2* gw = (const ulonglong2*)g_fc1bT;
        ulonglong2* sw2 = (ulonglong2*)sW;
        const ulonglong2* ga = (const ulonglong2*)g_act2T;
        ulonglong2* sa2 = (ulonglong2*)sA;
        for (int i = tid; i < 49 * 32; i += 256) {
            int k = i >> 5, r = i & 31;
            sw2[i] = gw[k * 1024 + (jb >> 1) + r];
            sa2[i] = ga[k * 512 + (sbs >> 1) + r];
        }
    }
    __syncthreads();

    int tj = tid & 15;         // 16 neuron groups (4 each)
    int ts = tid >> 4;         // 16 sample groups (4 each)

    int acc[4][4];
    #pragma unroll
    for (int i = 0; i < 4; i++)
        #pragma unroll
        for (int u = 0; u < 4; u++) acc[i][u] = 0;

    const ulonglong2* swv = (const ulonglong2*)sW;
    const ulonglong2* sav = (const ulonglong2*)sA;
    #pragma unroll 2
    for (int k = 0; k < 49; k++) {
        ulonglong2 w01 = swv[k * 32 + tj * 2];
        ulonglong2 w23 = swv[k * 32 + tj * 2 + 1];
        u64 wv[4] = {w01.x, w01.y, w23.x, w23.y};
        ulonglong2 a01 = sav[k * 32 + ts * 2];
        ulonglong2 a23 = sav[k * 32 + ts * 2 + 1];
        u64 av[4] = {a01.x, a01.y, a23.x, a23.y};
        #pragma unroll
        for (int i = 0; i < 4; i++)
            #pragma unroll
            for (int u = 0; u < 4; u++)
                acc[i][u] += __popcll(wv[i] ^ av[u]);
    }

    float nm[4], nsc[4], nbb[4];
    #pragma unroll
    for (int i = 0; i < 4; i++) {
        int j = jb + tj * 4 + i;
        nm[i]  = m3[j];
        nsc[i] = g3[j] * (1.0f / sqrtf(v3[j] + 1e-5f));
        nbb[i] = b3[j];
    }
    u32 nib[4];
    #pragma unroll
    for (int u = 0; u < 4; u++) {
        u32 nv = 0;
        #pragma unroll
        for (int i = 0; i < 4; i++) {
            float sum = (float)(3136 - 2 * acc[i][u]);
            if (((sum - nm[i]) * nsc[i] + nbb[i]) >= 0.f) nv |= 1u << i;
        }
        nib[u] = nv;
    }
    __syncthreads();
    unsigned char* bb = (unsigned char*)sA;   // [64 samples][16 bytes]
    #pragma unroll
    for (int u = 0; u < 4; u++)
        bb[(ts * 4 + u) * 16 + tj] = (unsigned char)nib[u];
    __syncthreads();
    if (tid < 128) {
        int s = tid >> 1, w = tid & 1;
        u64 v = ((const u64*)bb)[s * 2 + w];
        u64 tt = (v | (v >> 4)) & 0x00FF00FF00FF00FFull;
        tt = (tt | (tt >> 8)) & 0x0000FFFF0000FFFFull;
        u32 out = (u32)(tt | (tt >> 16));
        g_act3[(sbs + s) * 64 + (jb >> 5) + w] = out;
    }
}

// ---------------- stage 4: fc2 + scale ----------------
__global__ void k_fc2(const float* __restrict__ scale, float* __restrict__ out) {
    int idx = blockIdx.x * blockDim.x + threadIdx.x;
    if (idx >= 10240) return;
    int s = idx / 10, o = idx % 10;
    const u32* a = g_act3 + s * 64;
    const u32* w = g_fc2b + o * 64;
    int d = 0;
    #pragma unroll
    for (int k = 0; k < 64; k++) d += __popc(a[k] ^ w[k]);
    out[idx] = (float)(2048 - 2 * d) * scale[0];
}

// ---------------- launch ----------------
extern "C" void kernel_launch(void* const* d_in, const int* in_sizes, int n_in,
                              void* d_out, int out_size) {
    const float* x       = (const float*)d_in[0];
    const float* conv1_w = (const float*)d_in[1];
    const float* bn1_g   = (const float*)d_in[2];
    const float* bn1_b   = (const float*)d_in[3];
    const float* bn1_m   = (const float*)d_in[4];
    const float* bn1_v   = (const float*)d_in[5];
    const float* conv2_w = (const float*)d_in[6];
    const float* bn2_g   = (const float*)d_in[7];
    const float* bn2_b   = (const float*)d_in[8];
    const float* bn2_m   = (const float*)d_in[9];
    const float* bn2_v   = (const float*)d_in[10];
    const float* fc1_w   = (const float*)d_in[11];
    const float* bn3_g   = (const float*)d_in[12];
    const float* bn3_b   = (const float*)d_in[13];
    const float* bn3_m   = (const float*)d_in[14];
    const float* bn3_v   = (const float*)d_in[15];
    const float* fc2_w   = (const float*)d_in[16];
    const float* scale   = (const float*)d_in[17];
    float* out = (float*)d_out;

    k_packsmall<<<5, 256>>>(conv2_w, fc2_w);
    k_packfc1<<<2048, 128>>>(fc1_w);

    k_conv1<<<1024, 416>>>(x, conv1_w, bn1_g, bn1_b, bn1_m, bn1_v);
    k_conv2<<<256, 416>>>(bn2_g, bn2_b, bn2_m, bn2_v);

    cudaFuncSetAttribute(k_fc1, cudaFuncAttributeMaxDynamicSharedMemorySize, 50176);
    {
        dim3 grid(32, 16);   // 2048/64 neuron tiles, 1024/64 sample tiles
        k_fc1<<<grid, 256, 50176>>>(bn3_g, bn3_b, bn3_m, bn3_v);
    }
    k_fc2<<<40, 256>>>(scale, out);
}